// round 8
// baseline (speedup 1.0000x reference)
#include <cuda_runtime.h>
#include <cstdint>

// Problem constants
#define RR 4
#define ND 81
#define NB 4
#define NC 128
#define NH 96
#define NW 160

// Tiling (R4 geometry, scalar FFMA)
#define TX 32
#define YB 4
#define PX 4
#define XG 8
#define NDY 9
#define NTHREADS 288          // 9 warps
#define CCHUNK 8
#define NCHUNK 16
#define TGT_W 40              // TX + 2*RR
#define TGT_H 12              // YB + 2*RR
#define TGT_TILE (CCHUNK*TGT_H*TGT_W)    // 3840 floats
#define SRC_TILE (CCHUNK*YB*TX)          // 1024 floats
#define BUF_FLOATS (TGT_TILE + SRC_TILE) // 4864
#define BUF_BYTES (BUF_FLOATS*4)         // 19456
#define SMEM_BYTES (3*BUF_BYTES)         // 58368
#define NQUADS (BUF_FLOATS/4)            // 1216
#define MAXSLOTS 5
#define CBYTES (CCHUNK*NH*NW*4)

// Persistent scheduling
#define NTILES 480            // 5 x-tiles * 24 y-tiles * 4 batches
#define NBLOCKS 444           // 148 SMs * 3 resident blocks

__device__ int g_tile_counter;

__global__ void reset_counter_kernel() { g_tile_counter = 0; }

__device__ __forceinline__ int disp_index(int dyv, int dxv) {
    int ay = dyv < 0 ? -dyv : dyv;
    int ax = dxv < 0 ? -dxv : dxv;
    if ((ay | ax) == 0) return 0;
    if (ax == 0) return 1 + (ay - 1) * 20 + (dyv < 0 ? 0 : 1);
    if (ay == 0) return 1 + (ax - 1) * 20 + (dxv < 0 ? 2 : 3);
    int base = 1 + (ay - 1) * 20 + 4 + (ax - 1) * 4;
    if (dyv < 0 && dxv < 0) return base + 0;
    if (dyv > 0 && dxv > 0) return base + 1;
    if (dyv < 0 && dxv > 0) return base + 2;
    return base + 3;
}

__device__ __forceinline__ void cp_async16(uint32_t saddr, const void* gaddr, int sz) {
    asm volatile("cp.async.cg.shared.global [%0], [%1], 16, %2;\n"
                 :: "r"(saddr), "l"(gaddr), "r"(sz));
}
__device__ __forceinline__ void cp_commit() {
    asm volatile("cp.async.commit_group;\n" ::: "memory");
}

__global__ __launch_bounds__(NTHREADS, 3)
void costvol_kernel(const float* __restrict__ src,
                    const float* __restrict__ tgt,
                    float* __restrict__ out) {
    extern __shared__ __align__(16) float sm[];   // 3 * BUF_FLOATS
    __shared__ int s_tile;

    const int tid = threadIdx.x;

    // ---- compute role (fixed across tiles) ----
    const int xg   = tid & (XG - 1);
    const int dyi  = (tid >> 3) % NDY;
    const int yr   = tid / (XG * NDY);
    const int dyv  = dyi - RR;
    const int trow = yr + dyi;                       // 0..11
    const int t_off = trow * TGT_W + xg * PX;
    const int s_off = TGT_TILE + yr * TX + xg * PX;

    const uint32_t smem_base = (uint32_t)__cvta_generic_to_shared(&sm[0]);

    while (true) {
        if (tid == 0) s_tile = atomicAdd(&g_tile_counter, 1);
        __syncthreads();
        const int tile = s_tile;
        if (tile >= NTILES) return;
        __syncthreads();   // everyone read s_tile; smem buffers free from prev tile

        // tile -> (bx, by, b)
        const int b   = tile / 120;
        const int rem = tile % 120;
        const int by  = rem / 5;
        const int bx  = rem % 5;
        const int x0  = bx * TX;
        const int y0  = by * YB;

        const char* srcB = (const char*)(src + (size_t)b * NC * NH * NW);
        const char* tgtB = (const char*)(tgt + (size_t)b * NC * NH * NW);

        // ---- staging slots for this tile ----
        uint32_t goff[MAXSLOTS];
        uint32_t flags = 0;   // bit k: tgt slot; bit k+8: in-bounds
#pragma unroll
        for (int k = 0; k < MAXSLOTS; k++) {
            int idx = tid + k * NTHREADS;
            goff[k] = 0;
            if (idx < NQUADS) {
                if (idx < TGT_TILE / 4) {
                    int cc  = idx / (TGT_H * (TGT_W / 4));   // /120
                    int rm  = idx % (TGT_H * (TGT_W / 4));
                    int row = rm / (TGT_W / 4);              // /10
                    int xq  = rm % (TGT_W / 4);
                    int gy = y0 + row - RR;
                    int gx = x0 + xq * 4 - RR;
                    bool ok = ((unsigned)gy < NH) && ((unsigned)gx < NW);
                    if (ok) goff[k] = (uint32_t)(((cc * NH + gy) * NW + gx) * 4);
                    flags |= 1u << k;
                    if (ok) flags |= 1u << (k + 8);
                } else {
                    int q   = idx - TGT_TILE / 4;
                    int cc  = q / (YB * TX / 4);             // /32
                    int rm  = q % (YB * TX / 4);
                    int ry  = rm / (TX / 4);
                    int xq  = rm % (TX / 4);
                    goff[k] = (uint32_t)(((cc * NH + y0 + ry) * NW + x0 + xq * 4) * 4);
                    flags |= 1u << (k + 8);
                }
            }
        }

        float acc[NDY][PX];
#pragma unroll
        for (int i = 0; i < NDY; i++)
#pragma unroll
            for (int p = 0; p < PX; p++) acc[i][p] = 0.0f;

        auto stage = [&](int bi) {
            const uint32_t bofs = (uint32_t)bi * BUF_BYTES;
#pragma unroll
            for (int k = 0; k < MAXSLOTS; k++) {
                if (k < MAXSLOTS - 1 || tid < NQUADS - (MAXSLOTS - 1) * NTHREADS) {
                    const char* base = (flags >> k & 1) ? tgtB : srcB;
                    int sz = (flags >> (k + 8) & 1) ? 16 : 0;
                    cp_async16(smem_base + bofs + (uint32_t)(tid + k * NTHREADS) * 16,
                               base + goff[k], sz);
                    goff[k] += CBYTES;
                }
            }
            cp_commit();
        };

        stage(0);
        stage(1);

#pragma unroll 1
        for (int ch = 0; ch < NCHUNK; ch++) {
            if (ch + 2 < NCHUNK)
                asm volatile("cp.async.wait_group 1;\n" ::: "memory");
            else
                asm volatile("cp.async.wait_group 0;\n" ::: "memory");
            __syncthreads();

            const float* bp = sm + (ch % 3) * BUF_FLOATS;
            const float* tb = bp + t_off;
            const float* sb = bp + s_off;
#pragma unroll
            for (int cc = 0; cc < CCHUNK; cc++) {
                float4 s4 = *(const float4*)(sb + cc * (YB * TX));
                const float4* tq = (const float4*)(tb + cc * (TGT_H * TGT_W));
                float4 t0 = tq[0], t1 = tq[1], t2 = tq[2];
                float s[PX] = {s4.x, s4.y, s4.z, s4.w};
                float t[12] = {t0.x, t0.y, t0.z, t0.w,
                               t1.x, t1.y, t1.z, t1.w,
                               t2.x, t2.y, t2.z, t2.w};
#pragma unroll
                for (int dx = 0; dx < NDY; dx++)
#pragma unroll
                    for (int p = 0; p < PX; p++)
                        acc[dx][p] = fmaf(s[p], t[dx + p], acc[dx][p]);
            }

            if (ch + 2 < NCHUNK)
                stage((ch + 2) % 3);
        }

        // ---- epilogue: scale + scatter ----
        const float inv = 1.0f / 81.0f;
        const int y = y0 + yr;
#pragma unroll
        for (int dx = 0; dx < NDY; dx++) {
            int d = disp_index(dyv, dx - RR);
            float* o = out + ((((size_t)b * ND + d) * NH) + y) * NW + x0 + xg * PX;
            float4 v = make_float4(acc[dx][0] * inv, acc[dx][1] * inv,
                                   acc[dx][2] * inv, acc[dx][3] * inv);
            *(float4*)o = v;
        }

        __syncthreads();   // all reads of smem done before next tile restages
    }
}

extern "C" void kernel_launch(void* const* d_in, const int* in_sizes, int n_in,
                              void* d_out, int out_size) {
    const float* src = (const float*)d_in[0];
    const float* tgt = (const float*)d_in[1];
    float* out = (float*)d_out;

    cudaFuncSetAttribute(costvol_kernel,
                         cudaFuncAttributeMaxDynamicSharedMemorySize, SMEM_BYTES);

    reset_counter_kernel<<<1, 1>>>();
    costvol_kernel<<<NBLOCKS, NTHREADS, SMEM_BYTES>>>(src, tgt, out);
}

// round 9
// speedup vs baseline: 1.1163x; 1.1163x over previous
#include <cuda_runtime.h>
#include <cstdint>

// Problem constants
#define RR 4
#define ND 81
#define NB 4
#define NC 128
#define NH 96
#define NW 160

// Tiling (R4 geometry)
#define TX 32
#define YB 4
#define PX 4
#define XG 8
#define NDY 9
#define NTHREADS 288
#define CCHUNK 8
#define NCHUNK 16
#define TGT_W 40
#define TGT_H 12
#define TGT_TILE (CCHUNK*TGT_H*TGT_W)    // 3840 floats
#define SRC_TILE (CCHUNK*YB*TX)          // 1024 floats
#define BUF_FLOATS (TGT_TILE + SRC_TILE) // 4864
#define BUF_BYTES (BUF_FLOATS*4)         // 19456
#define SMEM_BYTES (3*BUF_BYTES)         // 58368
#define NQUADS (BUF_FLOATS/4)            // 1216
#define MAXSLOTS 5
#define CBYTES (CCHUNK*NH*NW*4)

// Split: kernel1 does tiles 0..443 (one perfect wave of 148*3),
// kernel2 does tiles 444..479 split 3-ways by dy.
#define K1_TILES 444
#define K2_TILES 36

// Kernel2 geometry: 96 threads, 3 dyi per block
#define NDYL 3
#define NTHREADS2 96
#define TGT_H2 6                          // rows g3..g3+5
#define TGT2_TILE (CCHUNK*TGT_H2*TGT_W)   // 1920 floats
#define BUF2_FLOATS (TGT2_TILE + SRC_TILE) // 2944
#define BUF2_BYTES (BUF2_FLOATS*4)         // 11776
#define SMEM2_BYTES (3*BUF2_BYTES)         // 35328
#define NQUADS2 (BUF2_FLOATS/4)            // 736 = 7*96 + 64
#define MAXSLOTS2 8

__device__ __forceinline__ int disp_index(int dyv, int dxv) {
    int ay = dyv < 0 ? -dyv : dyv;
    int ax = dxv < 0 ? -dxv : dxv;
    if ((ay | ax) == 0) return 0;
    if (ax == 0) return 1 + (ay - 1) * 20 + (dyv < 0 ? 0 : 1);
    if (ay == 0) return 1 + (ax - 1) * 20 + (dxv < 0 ? 2 : 3);
    int base = 1 + (ay - 1) * 20 + 4 + (ax - 1) * 4;
    if (dyv < 0 && dxv < 0) return base + 0;
    if (dyv > 0 && dxv > 0) return base + 1;
    if (dyv < 0 && dxv > 0) return base + 2;
    return base + 3;
}

__device__ __forceinline__ void cp_async16(uint32_t saddr, const void* gaddr, int sz) {
    asm volatile("cp.async.cg.shared.global [%0], [%1], 16, %2;\n"
                 :: "r"(saddr), "l"(gaddr), "r"(sz));
}
__device__ __forceinline__ void cp_commit() {
    asm volatile("cp.async.commit_group;\n" ::: "memory");
}

// ===================== Kernel 1: 444 uniform tiles =====================
__global__ __launch_bounds__(NTHREADS, 3)
void costvol_k1(const float* __restrict__ src,
                const float* __restrict__ tgt,
                float* __restrict__ out) {
    extern __shared__ __align__(16) float sm[];

    const int tid  = threadIdx.x;
    const int tile = blockIdx.x;           // 0..443
    const int b    = tile / 120;
    const int rem  = tile % 120;
    const int by   = rem / 5;
    const int bx   = rem % 5;
    const int x0   = bx * TX;
    const int y0   = by * YB;

    const char* srcB = (const char*)(src + (size_t)b * NC * NH * NW);
    const char* tgtB = (const char*)(tgt + (size_t)b * NC * NH * NW);

    uint32_t goff[MAXSLOTS];
    uint32_t flags = 0;
#pragma unroll
    for (int k = 0; k < MAXSLOTS; k++) {
        int idx = tid + k * NTHREADS;
        goff[k] = 0;
        if (idx < NQUADS) {
            if (idx < TGT_TILE / 4) {
                int cc  = idx / (TGT_H * (TGT_W / 4));
                int rm  = idx % (TGT_H * (TGT_W / 4));
                int row = rm / (TGT_W / 4);
                int xq  = rm % (TGT_W / 4);
                int gy = y0 + row - RR;
                int gx = x0 + xq * 4 - RR;
                bool ok = ((unsigned)gy < NH) && ((unsigned)gx < NW);
                if (ok) goff[k] = (uint32_t)(((cc * NH + gy) * NW + gx) * 4);
                flags |= 1u << k;
                if (ok) flags |= 1u << (k + 8);
            } else {
                int q   = idx - TGT_TILE / 4;
                int cc  = q / (YB * TX / 4);
                int rm  = q % (YB * TX / 4);
                int ry  = rm / (TX / 4);
                int xq  = rm % (TX / 4);
                goff[k] = (uint32_t)(((cc * NH + y0 + ry) * NW + x0 + xq * 4) * 4);
                flags |= 1u << (k + 8);
            }
        }
    }

    const uint32_t smem_base = (uint32_t)__cvta_generic_to_shared(&sm[0]);

    const int xg   = tid & (XG - 1);
    const int dyi  = (tid >> 3) % NDY;
    const int yr   = tid / (XG * NDY);
    const int dyv  = dyi - RR;
    const int trow = yr + dyi;
    const int t_off = trow * TGT_W + xg * PX;
    const int s_off = TGT_TILE + yr * TX + xg * PX;

    float acc[NDY][PX];
#pragma unroll
    for (int i = 0; i < NDY; i++)
#pragma unroll
        for (int p = 0; p < PX; p++) acc[i][p] = 0.0f;

    auto stage = [&](int bi) {
        const uint32_t bofs = (uint32_t)bi * BUF_BYTES;
#pragma unroll
        for (int k = 0; k < MAXSLOTS; k++) {
            if (k < MAXSLOTS - 1 || tid < NQUADS - (MAXSLOTS - 1) * NTHREADS) {
                const char* base = (flags >> k & 1) ? tgtB : srcB;
                int sz = (flags >> (k + 8) & 1) ? 16 : 0;
                cp_async16(smem_base + bofs + (uint32_t)(tid + k * NTHREADS) * 16,
                           base + goff[k], sz);
                goff[k] += CBYTES;
            }
        }
        cp_commit();
    };

    stage(0);
    stage(1);

#pragma unroll 1
    for (int ch = 0; ch < NCHUNK; ch++) {
        if (ch + 2 < NCHUNK)
            asm volatile("cp.async.wait_group 1;\n" ::: "memory");
        else
            asm volatile("cp.async.wait_group 0;\n" ::: "memory");
        __syncthreads();

        const float* bp = sm + (ch % 3) * BUF_FLOATS;
        const float* tb = bp + t_off;
        const float* sb = bp + s_off;
#pragma unroll
        for (int cc = 0; cc < CCHUNK; cc++) {
            float4 s4 = *(const float4*)(sb + cc * (YB * TX));
            const float4* tq = (const float4*)(tb + cc * (TGT_H * TGT_W));
            float4 t0 = tq[0], t1 = tq[1], t2 = tq[2];
            float s[PX] = {s4.x, s4.y, s4.z, s4.w};
            float t[12] = {t0.x, t0.y, t0.z, t0.w,
                           t1.x, t1.y, t1.z, t1.w,
                           t2.x, t2.y, t2.z, t2.w};
#pragma unroll
            for (int dx = 0; dx < NDY; dx++)
#pragma unroll
                for (int p = 0; p < PX; p++)
                    acc[dx][p] = fmaf(s[p], t[dx + p], acc[dx][p]);
        }

        if (ch + 2 < NCHUNK)
            stage((ch + 2) % 3);
    }

    const float inv = 1.0f / 81.0f;
    const int y = y0 + yr;
#pragma unroll
    for (int dx = 0; dx < NDY; dx++) {
        int d = disp_index(dyv, dx - RR);
        float* o = out + ((((size_t)b * ND + d) * NH) + y) * NW + x0 + xg * PX;
        float4 v = make_float4(acc[dx][0] * inv, acc[dx][1] * inv,
                               acc[dx][2] * inv, acc[dx][3] * inv);
        *(float4*)o = v;
    }
}

// ========== Kernel 2: 36 leftover tiles, split 3-ways by dy ==========
__global__ __launch_bounds__(NTHREADS2, 8)
void costvol_k2(const float* __restrict__ src,
                const float* __restrict__ tgt,
                float* __restrict__ out) {
    extern __shared__ __align__(16) float sm[];

    const int tid     = threadIdx.x;
    const int tile    = K1_TILES + blockIdx.x / NDYL;   // 444..479
    const int dygroup = blockIdx.x % NDYL;              // 0,1,2
    const int g3      = dygroup * 3;                    // first dyi of group

    const int b   = tile / 120;
    const int rem = tile % 120;
    const int by  = rem / 5;
    const int bx  = rem % 5;
    const int x0  = bx * TX;
    const int y0  = by * YB;

    const char* srcB = (const char*)(src + (size_t)b * NC * NH * NW);
    const char* tgtB = (const char*)(tgt + (size_t)b * NC * NH * NW);

    // staging: tgt rows [g3, g3+5] (6 rows) + full src tile
    uint32_t goff[MAXSLOTS2];
    uint32_t flags_t = 0;   // bit k: tgt slot
    uint32_t flags_b = 0;   // bit k: in-bounds
#pragma unroll
    for (int k = 0; k < MAXSLOTS2; k++) {
        int idx = tid + k * NTHREADS2;
        goff[k] = 0;
        if (idx < NQUADS2) {
            if (idx < TGT2_TILE / 4) {
                int cc  = idx / (TGT_H2 * (TGT_W / 4));   // /60
                int rm  = idx % (TGT_H2 * (TGT_W / 4));
                int row = rm / (TGT_W / 4);               // /10
                int xq  = rm % (TGT_W / 4);
                int gy = y0 + g3 + row - RR;
                int gx = x0 + xq * 4 - RR;
                bool ok = ((unsigned)gy < NH) && ((unsigned)gx < NW);
                if (ok) goff[k] = (uint32_t)(((cc * NH + gy) * NW + gx) * 4);
                flags_t |= 1u << k;
                if (ok) flags_b |= 1u << k;
            } else {
                int q   = idx - TGT2_TILE / 4;
                int cc  = q / (YB * TX / 4);              // /32
                int rm  = q % (YB * TX / 4);
                int ry  = rm / (TX / 4);
                int xq  = rm % (TX / 4);
                goff[k] = (uint32_t)(((cc * NH + y0 + ry) * NW + x0 + xq * 4) * 4);
                flags_b |= 1u << k;
            }
        }
    }

    const uint32_t smem_base = (uint32_t)__cvta_generic_to_shared(&sm[0]);

    // compute role: xg 0..7, dyl 0..2, yr 0..3
    const int xg  = tid & (XG - 1);
    const int dyl = (tid >> 3) % NDYL;
    const int yr  = tid / (XG * NDYL);
    const int dyi = g3 + dyl;
    const int dyv = dyi - RR;
    const int t_off = (yr + dyl) * TGT_W + xg * PX;     // local row yr+dyl in 6-row tile
    const int s_off = TGT2_TILE + yr * TX + xg * PX;

    float acc[NDY][PX];
#pragma unroll
    for (int i = 0; i < NDY; i++)
#pragma unroll
        for (int p = 0; p < PX; p++) acc[i][p] = 0.0f;

    auto stage = [&](int bi) {
        const uint32_t bofs = (uint32_t)bi * BUF2_BYTES;
#pragma unroll
        for (int k = 0; k < MAXSLOTS2; k++) {
            if (k < MAXSLOTS2 - 1 || tid < NQUADS2 - (MAXSLOTS2 - 1) * NTHREADS2) {
                const char* base = (flags_t >> k & 1) ? tgtB : srcB;
                int sz = (flags_b >> k & 1) ? 16 : 0;
                cp_async16(smem_base + bofs + (uint32_t)(tid + k * NTHREADS2) * 16,
                           base + goff[k], sz);
                goff[k] += CBYTES;
            }
        }
        cp_commit();
    };

    stage(0);
    stage(1);

#pragma unroll 1
    for (int ch = 0; ch < NCHUNK; ch++) {
        if (ch + 2 < NCHUNK)
            asm volatile("cp.async.wait_group 1;\n" ::: "memory");
        else
            asm volatile("cp.async.wait_group 0;\n" ::: "memory");
        __syncthreads();

        const float* bp = sm + (ch % 3) * BUF2_FLOATS;
        const float* tb = bp + t_off;
        const float* sb = bp + s_off;
#pragma unroll
        for (int cc = 0; cc < CCHUNK; cc++) {
            float4 s4 = *(const float4*)(sb + cc * (YB * TX));
            const float4* tq = (const float4*)(tb + cc * (TGT_H2 * TGT_W));
            float4 t0 = tq[0], t1 = tq[1], t2 = tq[2];
            float s[PX] = {s4.x, s4.y, s4.z, s4.w};
            float t[12] = {t0.x, t0.y, t0.z, t0.w,
                           t1.x, t1.y, t1.z, t1.w,
                           t2.x, t2.y, t2.z, t2.w};
#pragma unroll
            for (int dx = 0; dx < NDY; dx++)
#pragma unroll
                for (int p = 0; p < PX; p++)
                    acc[dx][p] = fmaf(s[p], t[dx + p], acc[dx][p]);
        }

        if (ch + 2 < NCHUNK)
            stage((ch + 2) % 3);
    }

    const float inv = 1.0f / 81.0f;
    const int y = y0 + yr;
#pragma unroll
    for (int dx = 0; dx < NDY; dx++) {
        int d = disp_index(dyv, dx - RR);
        float* o = out + ((((size_t)b * ND + d) * NH) + y) * NW + x0 + xg * PX;
        float4 v = make_float4(acc[dx][0] * inv, acc[dx][1] * inv,
                               acc[dx][2] * inv, acc[dx][3] * inv);
        *(float4*)o = v;
    }
}

extern "C" void kernel_launch(void* const* d_in, const int* in_sizes, int n_in,
                              void* d_out, int out_size) {
    const float* src = (const float*)d_in[0];
    const float* tgt = (const float*)d_in[1];
    float* out = (float*)d_out;

    cudaFuncSetAttribute(costvol_k1,
                         cudaFuncAttributeMaxDynamicSharedMemorySize, SMEM_BYTES);
    cudaFuncSetAttribute(costvol_k2,
                         cudaFuncAttributeMaxDynamicSharedMemorySize, SMEM2_BYTES);

    costvol_k1<<<K1_TILES, NTHREADS, SMEM_BYTES>>>(src, tgt, out);          // 444 blocks: one full wave
    costvol_k2<<<K2_TILES * NDYL, NTHREADS2, SMEM2_BYTES>>>(src, tgt, out); // 108 small blocks
}